// round 3
// baseline (speedup 1.0000x reference)
#include <cuda_runtime.h>

// Problem constants (fixed shapes from reference)
#define BS   1024        // B*S = 2*512
#define F    16384
#define D    768
#define M    262144
#define CHUNKS 16        // bs-chunks of 64 in main kernel (BS/64)

// ---------------- scratch (static device globals; no allocation) ----------------
__device__ __align__(16) float g_BT  [(size_t)F * D];   // up_decoder^T  [F, D]
__device__ __align__(16) float g_upT [(size_t)F * BS];  // up_facts^T    [F, BS]
__device__ __align__(16) float g_outT[(size_t)F * BS];  // out^T         [F, BS]
__device__ __align__(16) float g_vals[M];               // connection values
__device__ int            g_ii  [M];                    // normalized i indices
__device__ unsigned short g_jj  [M];                    // normalized j indices
__device__ int            g_rowptr[F + 1];              // CSR over sorted i
__device__ int            g_mode;                       // 1 = indices are int64, 0 = int32

// ---------------- dtype detection + index normalization -------------------------
__global__ void k_detect(const void* __restrict__ j_raw) {
    if (threadIdx.x == 0 && blockIdx.x == 0) {
        // j_indices are uniform random in [0,F). If the buffer is int32 and we
        // read int64, the high word is a random index -> value >= 2^32 almost
        // surely within 64 samples. 64 int64 reads = 512B <= M*4B, safe either way.
        const long long* p = (const long long*)j_raw;
        int ok = 1;
        for (int t = 0; t < 64; t++) {
            long long v = p[t];
            if (v < 0 || v >= F) { ok = 0; break; }
        }
        g_mode = ok;
    }
}

__global__ void k_decode(const void* __restrict__ i_raw, const void* __restrict__ j_raw) {
    int m = blockIdx.x * blockDim.x + threadIdx.x;
    if (m >= M) return;
    int iv, jv;
    if (g_mode) {
        iv = (int)((const long long*)i_raw)[m];
        jv = (int)((const long long*)j_raw)[m];
    } else {
        iv = ((const int*)i_raw)[m];
        jv = ((const int*)j_raw)[m];
    }
    g_ii[m] = iv;
    g_jj[m] = (unsigned short)jv;
}

// ---------------- build CSR row_ptr from sorted g_ii -----------------------------
__global__ void k_build() {
    int m = blockIdx.x * blockDim.x + threadIdx.x;
    if (m < M) {
        int cur  = g_ii[m];
        int prev = (m == 0) ? -1 : g_ii[m - 1];
        for (int f = prev + 1; f <= cur; f++) g_rowptr[f] = m;
    } else if (m == M) {
        int last = g_ii[M - 1];
        for (int f = last + 1; f <= F; f++) g_rowptr[f] = M;
    }
}

// ---------------- generic 32x32 tiled transpose: in [R,C] -> out [C,R] ----------
template<int R, int C>
__device__ __forceinline__ void transpose_body(const float* __restrict__ in,
                                               float* __restrict__ out) {
    __shared__ float tile[32][33];
    int cx = blockIdx.x * 32 + threadIdx.x;   // col in input
    int ry = blockIdx.y * 32 + threadIdx.y;   // row in input
#pragma unroll
    for (int k = 0; k < 32; k += 8)
        tile[threadIdx.y + k][threadIdx.x] = in[(size_t)(ry + k) * C + cx];
    __syncthreads();
    int ox = blockIdx.y * 32 + threadIdx.x;   // col in output (= input row)
    int oy = blockIdx.x * 32 + threadIdx.y;   // row in output (= input col)
#pragma unroll
    for (int k = 0; k < 32; k += 8)
        out[(size_t)(oy + k) * R + ox] = tile[threadIdx.x][threadIdx.y + k];
}

__global__ void k_t_updec(const float* __restrict__ in)  { transpose_body<D,  F >(in, g_BT);  }
__global__ void k_t_upfac(const float* __restrict__ in)  { transpose_body<BS, F >(in, g_upT); }
__global__ void k_t_out  (float* __restrict__ out)       { transpose_body<F,  BS>(g_outT, out); }

// ---------------- values[m] = <down_enc[i_m,:], BT[j_m,:]> ; warp per m ---------
__global__ void k_values(const float* __restrict__ de) {
    int w    = (blockIdx.x * blockDim.x + threadIdx.x) >> 5;   // exactly M warps
    int lane = threadIdx.x & 31;
    int i = __ldg(&g_ii[w]);
    int j = (int)__ldg(&g_jj[w]);
    const float4* a = (const float4*)(de   + (size_t)i * D);
    const float4* b = (const float4*)(g_BT + (size_t)j * D);
    float4 acc = make_float4(0.f, 0.f, 0.f, 0.f);
#pragma unroll
    for (int k = 0; k < (D / 4) / 32; k++) {        // 6 iterations, lane-strided
        float4 av = a[lane + 32 * k];
        float4 bv = b[lane + 32 * k];
        acc.x += av.x * bv.x; acc.y += av.y * bv.y;
        acc.z += av.z * bv.z; acc.w += av.w * bv.w;
    }
    float s = (acc.x + acc.y) + (acc.z + acc.w);
#pragma unroll
    for (int off = 16; off; off >>= 1) s += __shfl_xor_sync(0xffffffffu, s, off);
    if (lane == 0) g_vals[w] = s;
}

// ---------------- main: warp = (feature i, 64-wide bs-chunk), CSR reduce --------
__global__ void k_main() {
    int w     = (blockIdx.x * blockDim.x + threadIdx.x) >> 5;  // F*CHUNKS warps
    int lane  = threadIdx.x & 31;
    int i     = w >> 4;                 // / CHUNKS
    int chunk = w & (CHUNKS - 1);

    int start = g_rowptr[i];
    int end   = g_rowptr[i + 1];

    const float2* up2 = (const float2*)g_upT;
    int base2 = chunk * 32 + lane;      // float2 index within a BS-row (BS/2 = 512)

    float2 acc = make_float2(0.f, 0.f);
    for (int s0 = start; s0 < end; s0 += 32) {
        int idx = s0 + lane;
        int   jv = 0;
        float vv = 0.f;
        if (idx < end) { jv = (int)g_jj[idx]; vv = g_vals[idx]; }
        int n = min(32, end - s0);
        for (int t = 0; t < n; t++) {
            int   jt = __shfl_sync(0xffffffffu, jv, t);
            float vt = __shfl_sync(0xffffffffu, vv, t);
            float2 u = up2[(size_t)jt * (BS / 2) + base2];   // coalesced 256B/warp
            acc.x += vt * u.x;
            acc.y += vt * u.y;
        }
    }
    ((float2*)g_outT)[(size_t)i * (BS / 2) + base2] = acc;   // coalesced store
}

// ---------------- launch ---------------------------------------------------------
extern "C" void kernel_launch(void* const* d_in, const int* in_sizes, int n_in,
                              void* d_out, int out_size) {
    const float* up_facts = (const float*)d_in[0];     // [BS, F]
    const float* down_enc = (const float*)d_in[1];     // [F, D]
    const float* up_dec   = (const float*)d_in[2];     // [D, F]
    const void*  i_raw    = d_in[3];                   // [M] sorted (int32 or int64)
    const void*  j_raw    = d_in[4];                   // [M]
    float*       out      = (float*)d_out;             // [BS, F]

    dim3 tb(32, 8);
    k_detect <<<1, 32>>>(j_raw);
    k_decode <<<(M + 255) / 256, 256>>>(i_raw, j_raw); // -> g_ii, g_jj
    k_build  <<<(M + 256) / 256, 256>>>();             // -> g_rowptr
    k_t_updec<<<dim3(F / 32, D  / 32), tb>>>(up_dec);  // -> g_BT
    k_t_upfac<<<dim3(F / 32, BS / 32), tb>>>(up_facts);// -> g_upT
    k_values <<<M / 8, 256>>>(down_enc);               // -> g_vals
    k_main   <<<(F * CHUNKS) / 8, 256>>>();            // -> g_outT
    k_t_out  <<<dim3(BS / 32, F / 32), tb>>>(out);     // -> d_out
}

// round 5
// speedup vs baseline: 1.2914x; 1.2914x over previous
#include <cuda_runtime.h>
#include <cuda_fp16.h>

// Problem constants (fixed shapes from reference)
#define BS   1024        // B*S = 2*512
#define F    16384
#define D    768
#define M    262144
#define CHUNKS 8         // bs-chunks of 128 in main kernel (BS/128)

// ---------------- scratch (static device globals; no allocation) ----------------
__device__ __align__(16) __half g_BTh [(size_t)F * D];   // up_decoder^T  [F, D]  half (25 MB)
__device__ __align__(16) __half g_upTh[(size_t)F * BS];  // up_facts^T    [F, BS] half (34 MB)
__device__ __align__(16) float  g_outT[(size_t)F * BS];  // out^T         [F, BS] fp32 (67 MB)
__device__ __align__(16) float  g_vals[M];               // connection values
__device__ int            g_ii  [M];                     // normalized i indices
__device__ unsigned short g_jj  [M];                     // normalized j indices
__device__ int            g_rowptr[F + 1];               // CSR over sorted i
__device__ int            g_mode;                        // 1 = int64 indices, 0 = int32

// ---------------- dtype detection + index normalization -------------------------
__global__ void k_detect(const void* __restrict__ j_raw) {
    if (threadIdx.x == 0 && blockIdx.x == 0) {
        const long long* p = (const long long*)j_raw;
        int ok = 1;
        for (int t = 0; t < 64; t++) {
            long long v = p[t];
            if (v < 0 || v >= F) { ok = 0; break; }
        }
        g_mode = ok;
    }
}

__global__ void k_decode(const void* __restrict__ i_raw, const void* __restrict__ j_raw) {
    int m = blockIdx.x * blockDim.x + threadIdx.x;
    if (m >= M) return;
    int iv, jv;
    if (g_mode) {
        iv = (int)((const long long*)i_raw)[m];
        jv = (int)((const long long*)j_raw)[m];
    } else {
        iv = ((const int*)i_raw)[m];
        jv = ((const int*)j_raw)[m];
    }
    g_ii[m] = iv;
    g_jj[m] = (unsigned short)jv;
}

// ---------------- build CSR row_ptr from sorted g_ii -----------------------------
__global__ void k_build() {
    int m = blockIdx.x * blockDim.x + threadIdx.x;
    if (m < M) {
        int cur  = g_ii[m];
        int prev = (m == 0) ? -1 : g_ii[m - 1];
        for (int f = prev + 1; f <= cur; f++) g_rowptr[f] = m;
    } else if (m == M) {
        int last = g_ii[M - 1];
        for (int f = last + 1; f <= F; f++) g_rowptr[f] = M;
    }
}

// ------------- tiled transpose fp32 [R,C] -> half [C,R] --------------------------
template<int R, int C>
__device__ __forceinline__ void transpose_h_body(const float* __restrict__ in,
                                                 __half* __restrict__ out) {
    __shared__ float tile[32][33];
    int cx = blockIdx.x * 32 + threadIdx.x;   // col in input
    int ry = blockIdx.y * 32 + threadIdx.y;   // row in input
#pragma unroll
    for (int k = 0; k < 32; k += 8)
        tile[threadIdx.y + k][threadIdx.x] = in[(size_t)(ry + k) * C + cx];
    __syncthreads();
    int ox = blockIdx.y * 32 + threadIdx.x;
    int oy = blockIdx.x * 32 + threadIdx.y;
#pragma unroll
    for (int k = 0; k < 32; k += 8)
        out[(size_t)(oy + k) * R + ox] = __float2half_rn(tile[threadIdx.x][threadIdx.y + k]);
}

// ------------- tiled transpose fp32 [R,C] -> fp32 [C,R] --------------------------
template<int R, int C>
__device__ __forceinline__ void transpose_f_body(const float* __restrict__ in,
                                                 float* __restrict__ out) {
    __shared__ float tile[32][33];
    int cx = blockIdx.x * 32 + threadIdx.x;
    int ry = blockIdx.y * 32 + threadIdx.y;
#pragma unroll
    for (int k = 0; k < 32; k += 8)
        tile[threadIdx.y + k][threadIdx.x] = in[(size_t)(ry + k) * C + cx];
    __syncthreads();
    int ox = blockIdx.y * 32 + threadIdx.x;
    int oy = blockIdx.x * 32 + threadIdx.y;
#pragma unroll
    for (int k = 0; k < 32; k += 8)
        out[(size_t)(oy + k) * R + ox] = tile[threadIdx.x][threadIdx.y + k];
}

__global__ void k_t_updec(const float* __restrict__ in) { transpose_h_body<D,  F >(in, g_BTh);  }
__global__ void k_t_upfac(const float* __restrict__ in) { transpose_h_body<BS, F >(in, g_upTh); }
__global__ void k_t_out  (float* __restrict__ out)      { transpose_f_body<F,  BS>(g_outT, out); }

// -------- values[m] = <down_enc[i_m,:], BTh[j_m,:]> ; warp per m -----------------
__global__ void k_values(const float* __restrict__ de) {
    int w    = (blockIdx.x * blockDim.x + threadIdx.x) >> 5;   // exactly M warps
    int lane = threadIdx.x & 31;
    int i = __ldg(&g_ii[w]);
    int j = (int)__ldg(&g_jj[w]);
    const float2* a = (const float2*)(de + (size_t)i * D);         // 384 float2
    const half2*  b = (const half2*)(g_BTh + (size_t)j * D);       // 384 half2
    float acc = 0.f;
#pragma unroll
    for (int k = 0; k < (D / 2) / 32; k++) {        // 12 iterations, lane-strided
        float2 av = a[lane + 32 * k];
        float2 bv = __half22float2(b[lane + 32 * k]);
        acc += av.x * bv.x + av.y * bv.y;
    }
#pragma unroll
    for (int off = 16; off; off >>= 1) acc += __shfl_xor_sync(0xffffffffu, acc, off);
    if (lane == 0) g_vals[w] = acc;
}

// ---------------- main: warp = (feature i, 128-wide bs-chunk), CSR reduce --------
__global__ void k_main() {
    int w     = (blockIdx.x * blockDim.x + threadIdx.x) >> 5;  // F*CHUNKS warps
    int lane  = threadIdx.x & 31;
    int i     = w >> 3;                 // / CHUNKS
    int chunk = w & (CHUNKS - 1);

    int start = g_rowptr[i];
    int end   = g_rowptr[i + 1];

    const uint2* uph = (const uint2*)g_upTh;       // 4 halfs per uint2; row = BS/4 = 256
    int base4 = chunk * 32 + lane;                 // uint2 index within a row

    float4 acc = make_float4(0.f, 0.f, 0.f, 0.f);
    for (int s0 = start; s0 < end; s0 += 32) {
        int idx = s0 + lane;
        int   jv = 0;
        float vv = 0.f;
        if (idx < end) { jv = (int)g_jj[idx]; vv = g_vals[idx]; }
        int n = min(32, end - s0);
        for (int t = 0; t < n; t++) {
            int   jt = __shfl_sync(0xffffffffu, jv, t);
            float vt = __shfl_sync(0xffffffffu, vv, t);
            uint2 raw = uph[(size_t)jt * (BS / 4) + base4];   // 256B/warp coalesced
            float2 f0 = __half22float2(*(const half2*)&raw.x);
            float2 f1 = __half22float2(*(const half2*)&raw.y);
            acc.x += vt * f0.x;
            acc.y += vt * f0.y;
            acc.z += vt * f1.x;
            acc.w += vt * f1.y;
        }
    }
    ((float4*)g_outT)[(size_t)i * (BS / 4) + base4] = acc;    // 512B/warp coalesced
}

// ---------------- launch ---------------------------------------------------------
extern "C" void kernel_launch(void* const* d_in, const int* in_sizes, int n_in,
                              void* d_out, int out_size) {
    const float* up_facts = (const float*)d_in[0];     // [BS, F]
    const float* down_enc = (const float*)d_in[1];     // [F, D]
    const float* up_dec   = (const float*)d_in[2];     // [D, F]
    const void*  i_raw    = d_in[3];                   // [M] sorted (int32 or int64)
    const void*  j_raw    = d_in[4];                   // [M]
    float*       out      = (float*)d_out;             // [BS, F]

    dim3 tb(32, 8);
    k_detect <<<1, 32>>>(j_raw);
    k_decode <<<(M + 255) / 256, 256>>>(i_raw, j_raw); // -> g_ii, g_jj
    k_build  <<<(M + 256) / 256, 256>>>();             // -> g_rowptr
    k_t_updec<<<dim3(F / 32, D  / 32), tb>>>(up_dec);  // -> g_BTh (half)
    k_t_upfac<<<dim3(F / 32, BS / 32), tb>>>(up_facts);// -> g_upTh (half)
    k_values <<<M / 8, 256>>>(down_enc);               // -> g_vals
    k_main   <<<(F * CHUNKS) / 8, 256>>>();            // -> g_outT
    k_t_out  <<<dim3(BS / 32, F / 32), tb>>>(out);     // -> d_out
}

// round 6
// speedup vs baseline: 1.3608x; 1.0538x over previous
#include <cuda_runtime.h>
#include <cuda_fp16.h>

// Problem constants (fixed shapes from reference)
#define BS   1024        // B*S = 2*512
#define F    16384
#define D    768
#define M    262144
#define CHUNKS 8         // bs-chunks of 128 in main kernel (BS/128)

// ---------------- scratch (static device globals; no allocation) ----------------
__device__ __align__(16) __half g_BTh [(size_t)F * D];   // up_decoder^T  [F, D]  half
__device__ __align__(16) __half g_upTh[(size_t)F * BS];  // up_facts^T    [F, BS] half
__device__ __align__(16) float  g_vals[M];               // connection values
__device__ int            g_ii  [M];                     // normalized i indices
__device__ unsigned short g_jj  [M];                     // normalized j indices
__device__ int            g_rowptr[F + 1];               // CSR over sorted i
__device__ int            g_mode;                        // 1 = int64 indices, 0 = int32

// ---------------- dtype detection + index normalization -------------------------
__global__ void k_detect(const void* __restrict__ j_raw) {
    if (threadIdx.x == 0 && blockIdx.x == 0) {
        const long long* p = (const long long*)j_raw;
        int ok = 1;
        for (int t = 0; t < 64; t++) {
            long long v = p[t];
            if (v < 0 || v >= F) { ok = 0; break; }
        }
        g_mode = ok;
    }
}

__global__ void k_decode(const void* __restrict__ i_raw, const void* __restrict__ j_raw) {
    int m = blockIdx.x * blockDim.x + threadIdx.x;
    if (m >= M) return;
    int iv, jv;
    if (g_mode) {
        iv = (int)((const long long*)i_raw)[m];
        jv = (int)((const long long*)j_raw)[m];
    } else {
        iv = ((const int*)i_raw)[m];
        jv = ((const int*)j_raw)[m];
    }
    g_ii[m] = iv;
    g_jj[m] = (unsigned short)jv;
}

// ---------------- build CSR row_ptr from sorted g_ii -----------------------------
__global__ void k_build() {
    int m = blockIdx.x * blockDim.x + threadIdx.x;
    if (m < M) {
        int cur  = g_ii[m];
        int prev = (m == 0) ? -1 : g_ii[m - 1];
        for (int f = prev + 1; f <= cur; f++) g_rowptr[f] = m;
    } else if (m == M) {
        int last = g_ii[M - 1];
        for (int f = last + 1; f <= F; f++) g_rowptr[f] = M;
    }
}

// ------------- tiled transpose fp32 [R,C] -> half [C,R] --------------------------
template<int R, int C>
__device__ __forceinline__ void transpose_h_body(const float* __restrict__ in,
                                                 __half* __restrict__ out) {
    __shared__ float tile[32][33];
    int cx = blockIdx.x * 32 + threadIdx.x;   // col in input
    int ry = blockIdx.y * 32 + threadIdx.y;   // row in input
#pragma unroll
    for (int k = 0; k < 32; k += 8)
        tile[threadIdx.y + k][threadIdx.x] = in[(size_t)(ry + k) * C + cx];
    __syncthreads();
    int ox = blockIdx.y * 32 + threadIdx.x;
    int oy = blockIdx.x * 32 + threadIdx.y;
#pragma unroll
    for (int k = 0; k < 32; k += 8)
        out[(size_t)(oy + k) * R + ox] = __float2half_rn(tile[threadIdx.x][threadIdx.y + k]);
}

__global__ void k_t_updec(const float* __restrict__ in) { transpose_h_body<D,  F >(in, g_BTh);  }
__global__ void k_t_upfac(const float* __restrict__ in) { transpose_h_body<BS, F >(in, g_upTh); }

// -------- values[m] = <down_enc[i_m,:], BTh[j_m,:]> ; warp per m -----------------
__global__ void k_values(const float* __restrict__ de) {
    int w    = (blockIdx.x * blockDim.x + threadIdx.x) >> 5;   // exactly M warps
    int lane = threadIdx.x & 31;
    int i = __ldg(&g_ii[w]);
    int j = (int)__ldg(&g_jj[w]);
    const float2* a = (const float2*)(de + (size_t)i * D);         // 384 float2
    const half2*  b = (const half2*)(g_BTh + (size_t)j * D);       // 384 half2
    float acc = 0.f;
#pragma unroll
    for (int k = 0; k < (D / 2) / 32; k++) {        // 12 iterations, lane-strided
        float2 av = a[lane + 32 * k];
        float2 bv = __half22float2(b[lane + 32 * k]);
        acc += av.x * bv.x + av.y * bv.y;
    }
#pragma unroll
    for (int off = 16; off; off >>= 1) acc += __shfl_xor_sync(0xffffffffu, acc, off);
    if (lane == 0) g_vals[w] = acc;
}

// ------ main: block = 32 features x 128-bs chunk; CSR reduce; SMEM transpose -----
// Warp w handles feature i = blockIdx.x*32 + w over bs = blockIdx.y*128 .. +127.
// Accumulators in registers (float4 = 4 bs per lane); block-level shared transpose
// writes out[bs][i] directly (32 consecutive i per row = 128B coalesced stores),
// eliminating the outT intermediate and its transpose kernel entirely.
__global__ void __launch_bounds__(1024) k_main(float* __restrict__ out) {
    int warp = threadIdx.x >> 5;         // 0..31: feature offset within block
    int lane = threadIdx.x & 31;
    int i_base = blockIdx.x * 32;
    int chunk  = blockIdx.y;             // 0..CHUNKS-1
    int i = i_base + warp;

    int start = g_rowptr[i];
    int end   = g_rowptr[i + 1];

    const uint2* uph = (const uint2*)g_upTh;       // 4 halfs per uint2; row = BS/4 = 256
    int base4 = chunk * 32 + lane;                 // uint2 index within a row

    float4 acc = make_float4(0.f, 0.f, 0.f, 0.f);
    for (int s0 = start; s0 < end; s0 += 32) {
        int idx = s0 + lane;
        int   jv = 0;
        float vv = 0.f;
        if (idx < end) { jv = (int)g_jj[idx]; vv = g_vals[idx]; }
        int n = min(32, end - s0);
        for (int t = 0; t < n; t++) {
            int   jt = __shfl_sync(0xffffffffu, jv, t);
            float vt = __shfl_sync(0xffffffffu, vv, t);
            uint2 raw = uph[(size_t)jt * (BS / 4) + base4];   // 256B/warp coalesced
            float2 f0 = __half22float2(*(const half2*)&raw.x);
            float2 f1 = __half22float2(*(const half2*)&raw.y);
            acc.x += vt * f0.x;
            acc.y += vt * f0.y;
            acc.z += vt * f1.x;
            acc.w += vt * f1.y;
        }
    }

    // Block transpose: sm[feature][bs_local], padded to kill bank conflicts.
    __shared__ float sm[32][129];
    int b0 = lane * 4;
    sm[warp][b0 + 0] = acc.x;
    sm[warp][b0 + 1] = acc.y;
    sm[warp][b0 + 2] = acc.z;
    sm[warp][b0 + 3] = acc.w;
    __syncthreads();

#pragma unroll
    for (int r = 0; r < 4; r++) {
        int bs_local = warp * 4 + r;               // 32 warps x 4 rows = 128 bs rows
        int bs = chunk * 128 + bs_local;
        out[(size_t)bs * F + i_base + lane] = sm[lane][bs_local];  // 128B coalesced
    }
}

// ---------------- launch (fork-join stream capture for overlap) ------------------
extern "C" void kernel_launch(void* const* d_in, const int* in_sizes, int n_in,
                              void* d_out, int out_size) {
    const float* up_facts = (const float*)d_in[0];     // [BS, F]
    const float* down_enc = (const float*)d_in[1];     // [F, D]
    const float* up_dec   = (const float*)d_in[2];     // [D, F]
    const void*  i_raw    = d_in[3];                   // [M] sorted (int32 or int64)
    const void*  j_raw    = d_in[4];                   // [M]
    float*       out      = (float*)d_out;             // [BS, F]

    // One-time host resource creation (no device memory involved).
    static cudaStream_t s1 = nullptr, s2 = nullptr;
    static cudaEvent_t  e0, eDec, eVals, eUpfac;
    if (s1 == nullptr) {
        cudaStreamCreateWithFlags(&s1, cudaStreamNonBlocking);
        cudaStreamCreateWithFlags(&s2, cudaStreamNonBlocking);
        cudaEventCreateWithFlags(&e0,     cudaEventDisableTiming);
        cudaEventCreateWithFlags(&eDec,   cudaEventDisableTiming);
        cudaEventCreateWithFlags(&eVals,  cudaEventDisableTiming);
        cudaEventCreateWithFlags(&eUpfac, cudaEventDisableTiming);
    }
    cudaStream_t s0 = (cudaStream_t)0;   // legacy default stream (captured)

    dim3 tb(32, 8);
    // Fork: transposes on side streams, index pipeline on s0.
    cudaEventRecord(e0, s0);
    cudaStreamWaitEvent(s1, e0, 0);
    cudaStreamWaitEvent(s2, e0, 0);

    k_t_updec<<<dim3(F / 32, D  / 32), tb, 0, s1>>>(up_dec);    // -> g_BTh
    k_t_upfac<<<dim3(F / 32, BS / 32), tb, 0, s2>>>(up_facts);  // -> g_upTh
    cudaEventRecord(eUpfac, s2);

    k_detect <<<1, 32, 0, s0>>>(j_raw);
    k_decode <<<(M + 255) / 256, 256, 0, s0>>>(i_raw, j_raw);   // -> g_ii, g_jj
    cudaEventRecord(eDec, s0);
    k_build  <<<(M + 256) / 256, 256, 0, s0>>>();               // -> g_rowptr

    // values needs {decode, t_updec}: run on s1 after eDec.
    cudaStreamWaitEvent(s1, eDec, 0);
    k_values <<<M / 8, 256, 0, s1>>>(down_enc);                 // -> g_vals
    cudaEventRecord(eVals, s1);

    // main needs {build (s0), values (s1), t_upfac (s2)}.
    cudaStreamWaitEvent(s0, eVals, 0);
    cudaStreamWaitEvent(s0, eUpfac, 0);
    k_main   <<<dim3(F / 32, CHUNKS), 1024, 0, s0>>>(out);      // -> d_out directly
}